// round 13
// baseline (speedup 1.0000x reference)
#include <cuda_runtime.h>

#define NV 262144            // 64*64*64
#define BIGF 1e9f

// scratch: combined SIGNED fields, slots [field(2)][bc(16)][voxel]:
//   s = d_fg - d_bg, exactly one of (d_fg, d_bg) nonzero at every voxel.
//   Invariant holds after X pass and is preserved by Y/Z (and channel) passes.
__device__ float g_f[64ull * NV];
__device__ float g_acc[64];
__device__ unsigned g_cnt;

__device__ __forceinline__ float warpsum(float v) {
#pragma unroll
    for (int o = 16; o > 0; o >>= 1) v += __shfl_xor_sync(0xffffffffu, v, o);
    return v;
}

// squared dist to nearest set bit of `zeros` (BIGF if none)
__device__ __forceinline__ float dt1(unsigned long long zeros, int x) {
    unsigned long long below = zeros << (63 - x);      // bits <= x
    int dfwd = below ? __clzll((long long)below) : 1000;
    unsigned long long above = zeros >> x;             // bits >= x
    int dbwd = above ? (__ffsll((long long)above) - 1) : 1000;
    int d = min(dfwd, dbwd);
    return (d > 63) ? BIGF : (float)(d * d);
}

// ---------------- pass 1 (axis X) ----------------
// 1024 blocks x 512 threads. Block = one (b,c,y) group of 64 z-lines.
// Phase 1: 512 threads load 8 x's each -> 8-bit partial masks (pred lo, tgt hi).
// Phase 2: part = (field) x (x-quarter). 16 dt1 per thread; signed store.
__global__ void __launch_bounds__(512) k_pass1(const float* __restrict__ in, const int* __restrict__ tg) {
    if (blockIdx.x == 0) {       // reset accumulators for this replay
        if (threadIdx.x < 64) g_acc[threadIdx.x] = 0.0f;
        if (threadIdx.x == 64) g_cnt = 0u;
    }
    unsigned g = blockIdx.x;                 // (b,c,y)
    unsigned y = g & 63u, c = (g >> 6) & 7u, b = g >> 9;
    unsigned bc = b * 8u + c;
    int t = threadIdx.x;
    int z = t & 63;
    int part = t >> 6;                       // 0..7
    const float* pin = in + (size_t)bc * NV + y * 64u + z;
    const int*   ptg = tg + (size_t)b  * NV + y * 64u + z;

    unsigned m8 = 0u;                        // bits 0-7: pred, bits 8-15: tgt
#pragma unroll
    for (int k = 0; k < 8; ++k) {
        int x = part * 8 + k;
        float v = pin[(size_t)x * 4096];
        int   tt = ptg[(size_t)x * 4096];
        if (v > 0.5f)          m8 |= 1u << k;
        if ((unsigned)tt == c) m8 |= 1u << (8 + k);
    }
    __shared__ unsigned sm[512];
    sm[t] = m8;
    __syncthreads();

    int field   = part & 1;                  // 0 = pred, 1 = tgt
    int quarter = part >> 1;                 // x in [16*quarter, 16*quarter+16)
    unsigned long long m = 0ull;
#pragma unroll
    for (int p = 0; p < 8; ++p) {
        unsigned w = sm[z + p * 64];
        unsigned h8 = field ? ((w >> 8) & 0xFFu) : (w & 0xFFu);
        m |= (unsigned long long)h8 << (8 * p);
    }
    float* o = g_f + (size_t)(field * 16 + bc) * NV + y * 64u + z;
#pragma unroll 4
    for (int k = 0; k < 16; ++k) {
        int x = quarter * 16 + k;
        bool bit = ((m >> x) & 1ull) != 0ull;
        unsigned long long zz = bit ? ~m : m;        // zeros of the non-trivial side
        float dsq = dt1(zz, x);                      // always > 0
        o[(size_t)x * 4096] = bit ? dsq : -dsq;      // s = d_fg - d_bg
    }
}

// ---------------- fused Y+Z min-plus over one (y,z) plane in smem ----------------
// Exact: windowed min, pairs |i-j|<=3 (off^2<=9). If windowed min <= 16 it is
// the true min (outside pairs contribute >= 16); otherwise full-scan fallback.
template<int LSTRIDE, int LANESTRIDE>
__device__ __forceinline__ void pass_line(float* s, int t) {
    int lane = t & 63;           // orthogonal coordinate
    int h = t >> 6;              // 0..3 -> outputs i in [16h, 16h+16)
    float* bp = s + lane * LANESTRIDE;
    int jbase = 16 * h - 3;
    float fv[22];
#pragma unroll
    for (int k = 0; k < 22; ++k) {
        int j = jbase + k;
        fv[k] = (j >= 0 && j < 64) ? bp[j * LSTRIDE] : 3.0e38f;
    }
    float d[16];
#pragma unroll
    for (int a = 0; a < 16; ++a) d[a] = 3.0e38f;
#pragma unroll
    for (int k = 0; k < 14; ++k) {
#pragma unroll
        for (int a = 0; a < 8; ++a) {
            const int off = a + 3 - k;
            if (off * off <= 9) d[a] = fminf(d[a], fv[k] + (float)(off * off));
        }
    }
#pragma unroll
    for (int k = 8; k < 22; ++k) {
#pragma unroll
        for (int a = 8; a < 16; ++a) {
            const int off = a + 3 - k;
            if (off * off <= 9) d[a] = fminf(d[a], fv[k] + (float)(off * off));
        }
    }
    float mxA = d[0], mxB = d[8];
#pragma unroll
    for (int a = 1; a < 8; ++a) { mxA = fmaxf(mxA, d[a]); mxB = fmaxf(mxB, d[a + 8]); }
    if (mxA > 16.0f) {
#pragma unroll 1
        for (int j = 0; j < 64; ++j) {
            float fj = bp[j * LSTRIDE];
#pragma unroll
            for (int a = 0; a < 8; ++a) { int dd = 16 * h + a - j; d[a] = fminf(d[a], fj + (float)(dd * dd)); }
        }
    }
    if (mxB > 16.0f) {
#pragma unroll 1
        for (int j = 0; j < 64; ++j) {
            float fj = bp[j * LSTRIDE];
#pragma unroll
            for (int a = 8; a < 16; ++a) { int dd = 16 * h + a - j; d[a] = fminf(d[a], fj + (float)(dd * dd)); }
        }
    }
    __syncthreads();   // all reads (incl. fallback) done before anyone writes
#pragma unroll
    for (int a = 0; a < 16; ++a) bp[(16 * h + a) * LSTRIDE] = d[a];
    __syncthreads();
}

// 2048 blocks: (cvol = field*16+bc in 0..31) x (x in 0..63).
// Reads ONE combined signed plane, splits to fg/bg, runs Y+Z passes on both,
// re-encodes s = d_fg - d_bg (exactly one side nonzero) and writes IN PLACE.
__global__ void __launch_bounds__(256) k_pass23() {
    __shared__ float sf[64 * 65];
    __shared__ float sb[64 * 65];
    unsigned x = blockIdx.x & 63u, cvol = blockIdx.x >> 6;   // cvol < 32
    float* gio = g_f + (size_t)cvol * NV + x * 4096u;        // combined plane
    int t = threadIdx.x;
    {
        const float4* g4 = (const float4*)gio;
#pragma unroll
        for (int m = 0; m < 4; ++m) {
            int e4 = m * 256 + t;            // 1024 float4s
            float4 val = g4[e4];
            int e = e4 * 4;
            int y = e >> 6, z = e & 63;
            int idx = y * 65 + z;
            sf[idx + 0] = fmaxf(val.x, 0.0f); sb[idx + 0] = fmaxf(-val.x, 0.0f);
            sf[idx + 1] = fmaxf(val.y, 0.0f); sb[idx + 1] = fmaxf(-val.y, 0.0f);
            sf[idx + 2] = fmaxf(val.z, 0.0f); sb[idx + 2] = fmaxf(-val.z, 0.0f);
            sf[idx + 3] = fmaxf(val.w, 0.0f); sb[idx + 3] = fmaxf(-val.w, 0.0f);
        }
    }
    __syncthreads();
    pass_line<65, 1>(sf, t);   // Y pass, fg
    pass_line<65, 1>(sb, t);   // Y pass, bg
    pass_line<1, 65>(sf, t);   // Z pass, fg
    pass_line<1, 65>(sb, t);   // Z pass, bg
    {
        float4* g4 = (float4*)gio;
#pragma unroll
        for (int m = 0; m < 4; ++m) {
            int e4 = m * 256 + t;
            int e = e4 * 4;
            int y = e >> 6, z = e & 63;
            int idx = y * 65 + z;
            float4 val;
            val.x = sf[idx + 0] - sb[idx + 0];
            val.y = sf[idx + 1] - sb[idx + 1];
            val.z = sf[idx + 2] - sb[idx + 2];
            val.w = sf[idx + 3] - sb[idx + 3];
            g4[e4] = val;
        }
    }
}

// ---------------- fused stats + HD (+ channel EDT pass) + final ----------------
// 1024 blocks x 256 threads x 2 voxels = 524288 (b, voxel) entries
__global__ void __launch_bounds__(256) k_shd(const float* __restrict__ in, const int* __restrict__ tg,
                                             float* __restrict__ out) {
    unsigned E = (blockIdx.x * 256u + threadIdx.x) * 2u;
    unsigned v = E & (NV - 1u);
    unsigned b = E >> 18;

    float X[2][8];
#pragma unroll
    for (int c = 0; c < 8; ++c) {
        float2 t2 = *(const float2*)(in + (size_t)(b * 8 + c) * NV + v);
        X[0][c] = t2.x; X[1][c] = t2.y;
    }
    int T[2];
    { int2 tt = *(const int2*)(tg + (size_t)b * NV + v); T[0] = tt.x; T[1] = tt.y; }

    float tp[8], sP[8], cn[8];
#pragma unroll
    for (int c = 0; c < 8; ++c) { tp[c] = 0.f; sP[c] = 0.f; cn[c] = 0.f; }
    float ce = 0.0f, hd = 0.0f;

#pragma unroll
    for (int k = 0; k < 2; ++k) {
        float m = X[k][0];
#pragma unroll
        for (int c = 1; c < 8; ++c) m = fmaxf(m, X[k][c]);
        float e[8]; float S = 0.f;
#pragma unroll
        for (int c = 0; c < 8; ++c) { e[c] = exp2f((X[k][c] - m) * 1.4426950408889634f); S += e[c]; }
        float r = 1.0f / S;
        int t = T[k];
        float xt = X[k][0];
#pragma unroll
        for (int c = 0; c < 8; ++c) {
            float pr = e[c] * r;
            sP[c] += pr;
            bool is = (c == t);
            tp[c] += is ? pr : 0.0f;
            cn[c] += is ? 1.0f : 0.0f;
            xt     = is ? X[k][c] : xt;
        }
        ce += (m - xt) + __log2f(S) * 0.69314718055994531f;
    }

    // HD: per field, channel min-plus with the signed invariant:
    // at output i only the side matching sign(s_i) is nonzero, so
    // d(i) = dfg(i)+dbg(i) = min_j( (s_i>0 ? max(s_j,0) : max(-s_j,0)) + q_ij ).
#pragma unroll
    for (int field = 0; field < 2; ++field) {
        float A[2][8];
#pragma unroll
        for (int c = 0; c < 8; ++c) {
            float2 t2 = *(const float2*)(g_f + (size_t)(field * 16 + b * 8 + c) * NV + v);
            A[0][c] = t2.x; A[1][c] = t2.y;
        }
#pragma unroll
        for (int k = 0; k < 2; ++k) {
            float fgv[8], bgv[8];
#pragma unroll
            for (int c = 0; c < 8; ++c) {
                fgv[c] = fmaxf(A[k][c], 0.0f);
                bgv[c] = fmaxf(-A[k][c], 0.0f);
            }
            int t = T[k];
#pragma unroll
            for (int i = 0; i < 8; ++i) {
                bool pos = A[k][i] > 0.0f;           // s is never 0
                float m = 3.0e38f;
#pragma unroll
                for (int j = 0; j < 8; ++j) {
                    const float q = (float)((i - j) * (i - j));
                    float w = pos ? fgv[j] : bgv[j];
                    m = fminf(m, w + q);
                }
                float toh = (t == i) ? 1.0f : 0.0f;
                float pe = X[k][i] - toh;
                hd += pe * pe * m;
            }
        }
    }

    // warp reduce 26 scalars, then block-stage in smem, then 26 atomics per block
    __shared__ float sred[26 * 8];
    int w = threadIdx.x >> 5;
#pragma unroll
    for (int c = 0; c < 8; ++c) {
        float a  = warpsum(tp[c]);
        float s2 = warpsum(sP[c]);
        float q  = warpsum(cn[c]);
        if ((threadIdx.x & 31) == 0) {
            sred[c * 8 + w]        = a;
            sred[(8 + c) * 8 + w]  = s2;
            sred[(16 + c) * 8 + w] = q;
        }
    }
    float cs = warpsum(ce);
    float hs = warpsum(hd);
    if ((threadIdx.x & 31) == 0) { sred[24 * 8 + w] = cs; sred[25 * 8 + w] = hs; }
    __syncthreads();
    if (threadIdx.x < 26) {
        int i = threadIdx.x;
        float s = 0.f;
#pragma unroll
        for (int ww = 0; ww < 8; ++ww) s += sred[i * 8 + ww];
        float* dst;
        if (i < 8)       dst = &g_acc[b * 8 + i];
        else if (i < 16) dst = &g_acc[16 + b * 8 + (i - 8)];
        else if (i < 24) dst = &g_acc[32 + b * 8 + (i - 16)];
        else if (i == 24) dst = &g_acc[48];
        else              dst = &g_acc[49];
        atomicAdd(dst, s);
    }

    // last block finalizes (threadfence + completion counter)
    __threadfence();
    __syncthreads();
    if (threadIdx.x == 0) {
        unsigned done = atomicAdd(&g_cnt, 1u);
        if (done == gridDim.x - 1) {
            __threadfence();
            float diceAcc = 0.0f;
#pragma unroll
            for (int c = 1; c < 8; ++c) {
                float sb = 0.0f;
#pragma unroll
                for (int bb = 0; bb < 2; ++bb) {
                    float tps = g_acc[bb * 8 + c];
                    float sp  = g_acc[16 + bb * 8 + c];
                    float cnt = g_acc[32 + bb * 8 + c];
                    sb += 2.0f * tps / (sp + cnt + 1e-5f);   // alpha=beta=1
                }
                diceAcc += 0.5f * sb;
            }
            float dice = 1.0f - diceAcc * (1.0f / 7.0f);
            float cef = g_acc[48] * (1.0f / 524288.0f);
            float hdf = g_acc[49] * (1.0f / 4194304.0f);
            out[0] = dice + cef + hdf;
        }
    }
}

extern "C" void kernel_launch(void* const* d_in, const int* in_sizes, int n_in,
                              void* d_out, int out_size) {
    const float* in = (const float*)d_in[0];
    const int*   tg = (const int*)d_in[1];
    float* out = (float*)d_out;
    k_pass1 <<<1024, 512>>>(in, tg);
    k_pass23<<<2048, 256>>>();
    k_shd   <<<1024, 256>>>(in, tg, out);
}

// round 14
// speedup vs baseline: 1.0162x; 1.0162x over previous
#include <cuda_runtime.h>

#define NV 262144            // 64*64*64
#define BIGF 1e9f

// scratch: combined SIGNED fields, slots [field(2)][bc(16)][voxel]:
//   s = d_fg - d_bg, exactly one of (d_fg, d_bg) nonzero at every voxel.
//   Invariant holds after X pass and is preserved by Y/Z (and channel) passes.
__device__ float g_f[64ull * NV];
__device__ float g_part[26][1024];    // per-block partials, contention-free
__device__ unsigned g_cnt;

__device__ __forceinline__ float warpsum(float v) {
#pragma unroll
    for (int o = 16; o > 0; o >>= 1) v += __shfl_xor_sync(0xffffffffu, v, o);
    return v;
}

// squared dist to nearest set bit of `zeros` (BIGF if none)
__device__ __forceinline__ float dt1(unsigned long long zeros, int x) {
    unsigned long long below = zeros << (63 - x);      // bits <= x
    int dfwd = below ? __clzll((long long)below) : 1000;
    unsigned long long above = zeros >> x;             // bits >= x
    int dbwd = above ? (__ffsll((long long)above) - 1) : 1000;
    int d = min(dfwd, dbwd);
    return (d > 63) ? BIGF : (float)(d * d);
}

// ---------------- pass 1 (axis X) ----------------
// 1024 blocks x 512 threads. Block = one (b,c,y) group of 64 z-lines.
__global__ void __launch_bounds__(512) k_pass1(const float* __restrict__ in, const int* __restrict__ tg) {
    if (blockIdx.x == 0 && threadIdx.x == 0) g_cnt = 0u;   // reset for this replay
    unsigned g = blockIdx.x;                 // (b,c,y)
    unsigned y = g & 63u, c = (g >> 6) & 7u, b = g >> 9;
    unsigned bc = b * 8u + c;
    int t = threadIdx.x;
    int z = t & 63;
    int part = t >> 6;                       // 0..7
    const float* pin = in + (size_t)bc * NV + y * 64u + z;
    const int*   ptg = tg + (size_t)b  * NV + y * 64u + z;

    unsigned m8 = 0u;                        // bits 0-7: pred, bits 8-15: tgt
#pragma unroll
    for (int k = 0; k < 8; ++k) {
        int x = part * 8 + k;
        float v = pin[(size_t)x * 4096];
        int   tt = ptg[(size_t)x * 4096];
        if (v > 0.5f)          m8 |= 1u << k;
        if ((unsigned)tt == c) m8 |= 1u << (8 + k);
    }
    __shared__ unsigned sm[512];
    sm[t] = m8;
    __syncthreads();

    int field   = part & 1;                  // 0 = pred, 1 = tgt
    int quarter = part >> 1;                 // x in [16*quarter, 16*quarter+16)
    unsigned long long m = 0ull;
#pragma unroll
    for (int p = 0; p < 8; ++p) {
        unsigned w = sm[z + p * 64];
        unsigned h8 = field ? ((w >> 8) & 0xFFu) : (w & 0xFFu);
        m |= (unsigned long long)h8 << (8 * p);
    }
    float* o = g_f + (size_t)(field * 16 + bc) * NV + y * 64u + z;
#pragma unroll 4
    for (int k = 0; k < 16; ++k) {
        int x = quarter * 16 + k;
        bool bit = ((m >> x) & 1ull) != 0ull;
        unsigned long long zz = bit ? ~m : m;        // zeros of the non-trivial side
        float dsq = dt1(zz, x);                      // always > 0
        o[(size_t)x * 4096] = bit ? dsq : -dsq;      // s = d_fg - d_bg
    }
}

// ---------------- fused Y+Z min-plus over one (y,z) plane in smem ----------------
// Exact: windowed min, pairs |i-j|<=3 (off^2<=9). If windowed min <= 16 it is
// the true min (outside pairs contribute >= 16); otherwise full-scan fallback.
template<int LSTRIDE, int LANESTRIDE>
__device__ __forceinline__ void pass_line(float* s, int t) {
    int lane = t & 63;           // orthogonal coordinate
    int h = t >> 6;              // 0..3 -> outputs i in [16h, 16h+16)
    float* bp = s + lane * LANESTRIDE;
    int jbase = 16 * h - 3;
    float fv[22];
#pragma unroll
    for (int k = 0; k < 22; ++k) {
        int j = jbase + k;
        fv[k] = (j >= 0 && j < 64) ? bp[j * LSTRIDE] : 3.0e38f;
    }
    float d[16];
#pragma unroll
    for (int a = 0; a < 16; ++a) d[a] = 3.0e38f;
#pragma unroll
    for (int k = 0; k < 14; ++k) {
#pragma unroll
        for (int a = 0; a < 8; ++a) {
            const int off = a + 3 - k;
            if (off * off <= 9) d[a] = fminf(d[a], fv[k] + (float)(off * off));
        }
    }
#pragma unroll
    for (int k = 8; k < 22; ++k) {
#pragma unroll
        for (int a = 8; a < 16; ++a) {
            const int off = a + 3 - k;
            if (off * off <= 9) d[a] = fminf(d[a], fv[k] + (float)(off * off));
        }
    }
    float mxA = d[0], mxB = d[8];
#pragma unroll
    for (int a = 1; a < 8; ++a) { mxA = fmaxf(mxA, d[a]); mxB = fmaxf(mxB, d[a + 8]); }
    if (mxA > 16.0f) {
#pragma unroll 1
        for (int j = 0; j < 64; ++j) {
            float fj = bp[j * LSTRIDE];
#pragma unroll
            for (int a = 0; a < 8; ++a) { int dd = 16 * h + a - j; d[a] = fminf(d[a], fj + (float)(dd * dd)); }
        }
    }
    if (mxB > 16.0f) {
#pragma unroll 1
        for (int j = 0; j < 64; ++j) {
            float fj = bp[j * LSTRIDE];
#pragma unroll
            for (int a = 8; a < 16; ++a) { int dd = 16 * h + a - j; d[a] = fminf(d[a], fj + (float)(dd * dd)); }
        }
    }
    __syncthreads();   // all reads (incl. fallback) done before anyone writes
#pragma unroll
    for (int a = 0; a < 16; ++a) bp[(16 * h + a) * LSTRIDE] = d[a];
    __syncthreads();
}

// 2048 blocks: (cvol = field*16+bc in 0..31) x (x in 0..63).
// Reads ONE combined signed plane, splits to fg/bg, runs Y+Z passes on both,
// re-encodes s = d_fg - d_bg and writes IN PLACE.
__global__ void __launch_bounds__(256) k_pass23() {
    __shared__ float sf[64 * 65];
    __shared__ float sb[64 * 65];
    unsigned x = blockIdx.x & 63u, cvol = blockIdx.x >> 6;   // cvol < 32
    float* gio = g_f + (size_t)cvol * NV + x * 4096u;        // combined plane
    int t = threadIdx.x;
    {
        const float4* g4 = (const float4*)gio;
#pragma unroll
        for (int m = 0; m < 4; ++m) {
            int e4 = m * 256 + t;            // 1024 float4s
            float4 val = g4[e4];
            int e = e4 * 4;
            int y = e >> 6, z = e & 63;
            int idx = y * 65 + z;
            sf[idx + 0] = fmaxf(val.x, 0.0f); sb[idx + 0] = fmaxf(-val.x, 0.0f);
            sf[idx + 1] = fmaxf(val.y, 0.0f); sb[idx + 1] = fmaxf(-val.y, 0.0f);
            sf[idx + 2] = fmaxf(val.z, 0.0f); sb[idx + 2] = fmaxf(-val.z, 0.0f);
            sf[idx + 3] = fmaxf(val.w, 0.0f); sb[idx + 3] = fmaxf(-val.w, 0.0f);
        }
    }
    __syncthreads();
    pass_line<65, 1>(sf, t);   // Y pass, fg
    pass_line<65, 1>(sb, t);   // Y pass, bg
    pass_line<1, 65>(sf, t);   // Z pass, fg
    pass_line<1, 65>(sb, t);   // Z pass, bg
    {
        float4* g4 = (float4*)gio;
#pragma unroll
        for (int m = 0; m < 4; ++m) {
            int e4 = m * 256 + t;
            int e = e4 * 4;
            int y = e >> 6, z = e & 63;
            int idx = y * 65 + z;
            float4 val;
            val.x = sf[idx + 0] - sb[idx + 0];
            val.y = sf[idx + 1] - sb[idx + 1];
            val.z = sf[idx + 2] - sb[idx + 2];
            val.w = sf[idx + 3] - sb[idx + 3];
            g4[e4] = val;
        }
    }
}

// ---------------- full min-plus over channel axis, length 8, branchless ----------------
__device__ __forceinline__ void minplus8(const float* __restrict__ a, float* __restrict__ d) {
#pragma unroll
    for (int i = 0; i < 8; ++i) {
        float m = 3.0e38f;
#pragma unroll
        for (int j = 0; j < 8; ++j) {
            const float q = (float)((i - j) * (i - j));
            m = fminf(m, a[j] + q);
        }
        d[i] = m;
    }
}

// ---------------- fused stats + HD (+ channel EDT pass) + final ----------------
// 1024 blocks x 256 threads x 2 voxels = 524288 (b, voxel) entries
__global__ void __launch_bounds__(256) k_shd(const float* __restrict__ in, const int* __restrict__ tg,
                                             float* __restrict__ out) {
    unsigned E = (blockIdx.x * 256u + threadIdx.x) * 2u;
    unsigned v = E & (NV - 1u);
    unsigned b = E >> 18;

    float X[2][8];
#pragma unroll
    for (int c = 0; c < 8; ++c) {
        float2 t2 = *(const float2*)(in + (size_t)(b * 8 + c) * NV + v);
        X[0][c] = t2.x; X[1][c] = t2.y;
    }
    int T[2];
    { int2 tt = *(const int2*)(tg + (size_t)b * NV + v); T[0] = tt.x; T[1] = tt.y; }

    float tp[8], sP[8], cn[8];
#pragma unroll
    for (int c = 0; c < 8; ++c) { tp[c] = 0.f; sP[c] = 0.f; cn[c] = 0.f; }
    float ce = 0.0f, hd = 0.0f;

#pragma unroll
    for (int k = 0; k < 2; ++k) {
        float m = X[k][0];
#pragma unroll
        for (int c = 1; c < 8; ++c) m = fmaxf(m, X[k][c]);
        float e[8]; float S = 0.f;
#pragma unroll
        for (int c = 0; c < 8; ++c) { e[c] = exp2f((X[k][c] - m) * 1.4426950408889634f); S += e[c]; }
        float r = 1.0f / S;
        int t = T[k];
        float xt = X[k][0];
#pragma unroll
        for (int c = 0; c < 8; ++c) {
            float pr = e[c] * r;
            sP[c] += pr;
            bool is = (c == t);
            tp[c] += is ? pr : 0.0f;
            cn[c] += is ? 1.0f : 0.0f;
            xt     = is ? X[k][c] : xt;
        }
        ce += (m - xt) + __log2f(S) * 0.69314718055994531f;
    }

    // HD: per field, decode combined signed field into fg/bg, dual min-plus
    // (branchless, exact), accumulate pe^2 * (d_fg + d_bg).
#pragma unroll
    for (int field = 0; field < 2; ++field) {
        float A[2][8];
#pragma unroll
        for (int c = 0; c < 8; ++c) {
            float2 t2 = *(const float2*)(g_f + (size_t)(field * 16 + b * 8 + c) * NV + v);
            A[0][c] = t2.x; A[1][c] = t2.y;
        }
#pragma unroll
        for (int k = 0; k < 2; ++k) {
            float fgv[8], bgv[8];
#pragma unroll
            for (int c = 0; c < 8; ++c) {
                fgv[c] = fmaxf(A[k][c], 0.0f);
                bgv[c] = fmaxf(-A[k][c], 0.0f);
            }
            float dfg[8], dbg[8];
            minplus8(fgv, dfg);
            minplus8(bgv, dbg);
            int t = T[k];
#pragma unroll
            for (int c = 0; c < 8; ++c) {
                float toh = (t == c) ? 1.0f : 0.0f;
                float pe = X[k][c] - toh;
                hd += pe * pe * (dfg[c] + dbg[c]);
            }
        }
    }

    // warp reduce 26 scalars -> smem -> per-block partial stores (NO atomics)
    __shared__ float sred[26 * 8];
    int w = threadIdx.x >> 5;
#pragma unroll
    for (int c = 0; c < 8; ++c) {
        float a  = warpsum(tp[c]);
        float s2 = warpsum(sP[c]);
        float q  = warpsum(cn[c]);
        if ((threadIdx.x & 31) == 0) {
            sred[c * 8 + w]        = a;
            sred[(8 + c) * 8 + w]  = s2;
            sred[(16 + c) * 8 + w] = q;
        }
    }
    float cs = warpsum(ce);
    float hs = warpsum(hd);
    if ((threadIdx.x & 31) == 0) { sred[24 * 8 + w] = cs; sred[25 * 8 + w] = hs; }
    __syncthreads();
    // layout of 26 accumulators: [0..7]=tp(b*8+c merged below), [8..15]=sP, [16..23]=cn, 24=ce, 25=hd
    // NOTE: tp/sP/cn are per (b,c); b is constant per block, so store under c and
    // merge per-b at finalize using the block id (blocks 0..511 are b=0, 512..1023 b=1).
    if (threadIdx.x < 26) {
        int i = threadIdx.x;
        float s = 0.f;
#pragma unroll
        for (int ww = 0; ww < 8; ++ww) s += sred[i * 8 + ww];
        g_part[i][blockIdx.x] = s;
        __threadfence();             // writers only: order stores before counter
    }
    __syncthreads();

    // last block finalizes (completion counter)
    if (threadIdx.x == 0) {
        unsigned done = atomicAdd(&g_cnt, 1u);
        sred[0] = (done == gridDim.x - 1) ? 1.0f : 0.0f;
    }
    __syncthreads();
    if (sred[0] != 0.0f) {
        // reduce g_part[i][0..1023]; for i<24 split per-b: blocks [0,512) are b=0.
        __shared__ float facc[26][2];
        int lane = threadIdx.x & 31;
        int wi = threadIdx.x >> 5;       // 8 warps
#pragma unroll
        for (int iter = 0; iter < 4; ++iter) {
            int i = iter * 8 + wi;
            if (i < 26) {
                const volatile float* p = g_part[i];
                float s0 = 0.f, s1 = 0.f;
#pragma unroll
                for (int k = 0; k < 16; ++k) s0 += p[k * 32 + lane];          // blocks 0..511
#pragma unroll
                for (int k = 16; k < 32; ++k) s1 += p[k * 32 + lane];         // blocks 512..1023
                s0 = warpsum(s0); s1 = warpsum(s1);
                if (lane == 0) { facc[i][0] = s0; facc[i][1] = s1; }
            }
        }
        __syncthreads();
        if (threadIdx.x == 0) {
            float diceAcc = 0.0f;
#pragma unroll
            for (int c = 1; c < 8; ++c) {
                float sb2 = 0.0f;
#pragma unroll
                for (int bb = 0; bb < 2; ++bb) {
                    float tps = facc[c][bb];
                    float sp  = facc[8 + c][bb];
                    float cnt = facc[16 + c][bb];
                    sb2 += 2.0f * tps / (sp + cnt + 1e-5f);   // alpha=beta=1
                }
                diceAcc += 0.5f * sb2;
            }
            float dice = 1.0f - diceAcc * (1.0f / 7.0f);
            float cef = (facc[24][0] + facc[24][1]) * (1.0f / 524288.0f);
            float hdf = (facc[25][0] + facc[25][1]) * (1.0f / 4194304.0f);
            out[0] = dice + cef + hdf;
        }
    }
}

extern "C" void kernel_launch(void* const* d_in, const int* in_sizes, int n_in,
                              void* d_out, int out_size) {
    const float* in = (const float*)d_in[0];
    const int*   tg = (const int*)d_in[1];
    float* out = (float*)d_out;
    k_pass1 <<<1024, 512>>>(in, tg);
    k_pass23<<<2048, 256>>>();
    k_shd   <<<1024, 256>>>(in, tg, out);
}

// round 15
// speedup vs baseline: 1.0542x; 1.0374x over previous
#include <cuda_runtime.h>

#define NV 262144            // 64*64*64
#define BIGF 1e9f

// scratch: combined SIGNED fields, slots [field(2)][bc(16)][voxel]:
//   s = d_fg - d_bg, exactly one of (d_fg, d_bg) nonzero at every voxel.
//   Invariant holds after X pass and is preserved by Y/Z (and channel) passes.
__device__ float g_f[64ull * NV];
__device__ float g_part[26][1024];    // per-block partials, contention-free
__device__ unsigned g_cnt;

__device__ __forceinline__ float warpsum(float v) {
#pragma unroll
    for (int o = 16; o > 0; o >>= 1) v += __shfl_xor_sync(0xffffffffu, v, o);
    return v;
}

// squared dist to nearest set bit of `zeros` (BIGF if none)
__device__ __forceinline__ float dt1(unsigned long long zeros, int x) {
    unsigned long long below = zeros << (63 - x);      // bits <= x
    int dfwd = below ? __clzll((long long)below) : 1000;
    unsigned long long above = zeros >> x;             // bits >= x
    int dbwd = above ? (__ffsll((long long)above) - 1) : 1000;
    int d = min(dfwd, dbwd);
    return (d > 63) ? BIGF : (float)(d * d);
}

// quarter templated: after unroll, x is a compile-time constant -> immediate shifts
template<int Q>
__device__ __forceinline__ void p1_store(unsigned long long m, float* o) {
#pragma unroll
    for (int k = 0; k < 16; ++k) {
        const int x = Q * 16 + k;
        bool bit = ((m >> x) & 1ull) != 0ull;
        unsigned long long zz = bit ? ~m : m;        // zeros of the non-trivial side
        float dsq = dt1(zz, x);                      // always > 0
        o[(size_t)x * 4096] = bit ? dsq : -dsq;      // s = d_fg - d_bg
    }
}

// ---------------- pass 1 (axis X) ----------------
// 1024 blocks x 512 threads. Block = one (b,c,y) group of 64 z-lines.
__global__ void __launch_bounds__(512) k_pass1(const float* __restrict__ in, const int* __restrict__ tg) {
    if (blockIdx.x == 0 && threadIdx.x == 0) g_cnt = 0u;   // reset for this replay
    unsigned g = blockIdx.x;                 // (b,c,y)
    unsigned y = g & 63u, c = (g >> 6) & 7u, b = g >> 9;
    unsigned bc = b * 8u + c;
    int t = threadIdx.x;
    int z = t & 63;
    int part = t >> 6;                       // 0..7
    const float* pin = in + (size_t)bc * NV + y * 64u + z;
    const int*   ptg = tg + (size_t)b  * NV + y * 64u + z;

    unsigned m8 = 0u;                        // bits 0-7: pred, bits 8-15: tgt
#pragma unroll
    for (int k = 0; k < 8; ++k) {
        int x = part * 8 + k;
        float v = pin[(size_t)x * 4096];
        int   tt = ptg[(size_t)x * 4096];
        if (v > 0.5f)          m8 |= 1u << k;
        if ((unsigned)tt == c) m8 |= 1u << (8 + k);
    }
    __shared__ unsigned sm[512];
    sm[t] = m8;
    __syncthreads();

    int field   = part & 1;                  // 0 = pred, 1 = tgt
    int quarter = part >> 1;                 // x in [16*quarter, 16*quarter+16)
    unsigned long long m = 0ull;
#pragma unroll
    for (int p = 0; p < 8; ++p) {
        unsigned w = sm[z + p * 64];
        unsigned h8 = field ? ((w >> 8) & 0xFFu) : (w & 0xFFu);
        m |= (unsigned long long)h8 << (8 * p);
    }
    float* o = g_f + (size_t)(field * 16 + bc) * NV + y * 64u + z;
    switch (quarter) {                       // warp-uniform
        case 0: p1_store<0>(m, o); break;
        case 1: p1_store<1>(m, o); break;
        case 2: p1_store<2>(m, o); break;
        default: p1_store<3>(m, o); break;
    }
}

// ---------------- fused Y+Z min-plus over one (y,z) plane in smem ----------------
// Exact: windowed min, pairs |i-j|<=3 (off^2<=9). If windowed min <= 16 it is
// the true min (outside pairs contribute >= 16); otherwise full-scan fallback.
// NOTE: no trailing sync — the NEXT pass_line's internal sync (or the kernel's
// explicit sync before the store) orders these writes before their readers.
template<int LSTRIDE, int LANESTRIDE>
__device__ __forceinline__ void pass_line(float* s, int t) {
    int lane = t & 63;           // orthogonal coordinate
    int h = t >> 6;              // 0..3 -> outputs i in [16h, 16h+16)
    float* bp = s + lane * LANESTRIDE;
    int jbase = 16 * h - 3;
    float fv[22];
#pragma unroll
    for (int k = 0; k < 22; ++k) {
        int j = jbase + k;
        fv[k] = (j >= 0 && j < 64) ? bp[j * LSTRIDE] : 3.0e38f;
    }
    float d[16];
#pragma unroll
    for (int a = 0; a < 16; ++a) d[a] = 3.0e38f;
#pragma unroll
    for (int k = 0; k < 14; ++k) {
#pragma unroll
        for (int a = 0; a < 8; ++a) {
            const int off = a + 3 - k;
            if (off * off <= 9) d[a] = fminf(d[a], fv[k] + (float)(off * off));
        }
    }
#pragma unroll
    for (int k = 8; k < 22; ++k) {
#pragma unroll
        for (int a = 8; a < 16; ++a) {
            const int off = a + 3 - k;
            if (off * off <= 9) d[a] = fminf(d[a], fv[k] + (float)(off * off));
        }
    }
    float mxA = d[0], mxB = d[8];
#pragma unroll
    for (int a = 1; a < 8; ++a) { mxA = fmaxf(mxA, d[a]); mxB = fmaxf(mxB, d[a + 8]); }
    if (mxA > 16.0f) {
#pragma unroll 1
        for (int j = 0; j < 64; ++j) {
            float fj = bp[j * LSTRIDE];
#pragma unroll
            for (int a = 0; a < 8; ++a) { int dd = 16 * h + a - j; d[a] = fminf(d[a], fj + (float)(dd * dd)); }
        }
    }
    if (mxB > 16.0f) {
#pragma unroll 1
        for (int j = 0; j < 64; ++j) {
            float fj = bp[j * LSTRIDE];
#pragma unroll
            for (int a = 8; a < 16; ++a) { int dd = 16 * h + a - j; d[a] = fminf(d[a], fj + (float)(dd * dd)); }
        }
    }
    __syncthreads();   // all reads (incl. fallback) done before anyone writes
#pragma unroll
    for (int a = 0; a < 16; ++a) bp[(16 * h + a) * LSTRIDE] = d[a];
}

// 2048 blocks: (cvol = field*16+bc in 0..31) x (x in 0..63).
// Reads ONE combined signed plane, splits to fg/bg, runs Y+Z passes on both,
// re-encodes s = d_fg - d_bg and writes IN PLACE.
__global__ void __launch_bounds__(256) k_pass23() {
    __shared__ float sf[64 * 65];
    __shared__ float sb[64 * 65];
    unsigned x = blockIdx.x & 63u, cvol = blockIdx.x >> 6;   // cvol < 32
    float* gio = g_f + (size_t)cvol * NV + x * 4096u;        // combined plane
    int t = threadIdx.x;
    {
        const float4* g4 = (const float4*)gio;
#pragma unroll
        for (int m = 0; m < 4; ++m) {
            int e4 = m * 256 + t;            // 1024 float4s
            float4 val = g4[e4];
            int e = e4 * 4;
            int y = e >> 6, z = e & 63;
            int idx = y * 65 + z;
            sf[idx + 0] = fmaxf(val.x, 0.0f); sb[idx + 0] = fmaxf(-val.x, 0.0f);
            sf[idx + 1] = fmaxf(val.y, 0.0f); sb[idx + 1] = fmaxf(-val.y, 0.0f);
            sf[idx + 2] = fmaxf(val.z, 0.0f); sb[idx + 2] = fmaxf(-val.z, 0.0f);
            sf[idx + 3] = fmaxf(val.w, 0.0f); sb[idx + 3] = fmaxf(-val.w, 0.0f);
        }
    }
    __syncthreads();
    pass_line<65, 1>(sf, t);   // Y pass, fg   (writes sf; ordered by sb-pass sync)
    pass_line<65, 1>(sb, t);   // Y pass, bg
    pass_line<1, 65>(sf, t);   // Z pass, fg
    pass_line<1, 65>(sb, t);   // Z pass, bg
    __syncthreads();           // order bg-Z writes before the store reads
    {
        float4* g4 = (float4*)gio;
#pragma unroll
        for (int m = 0; m < 4; ++m) {
            int e4 = m * 256 + t;
            int e = e4 * 4;
            int y = e >> 6, z = e & 63;
            int idx = y * 65 + z;
            float4 val;
            val.x = sf[idx + 0] - sb[idx + 0];
            val.y = sf[idx + 1] - sb[idx + 1];
            val.z = sf[idx + 2] - sb[idx + 2];
            val.w = sf[idx + 3] - sb[idx + 3];
            g4[e4] = val;
        }
    }
}

// ---------------- full min-plus over channel axis, length 8, branchless ----------------
__device__ __forceinline__ void minplus8(const float* __restrict__ a, float* __restrict__ d) {
#pragma unroll
    for (int i = 0; i < 8; ++i) {
        float m = 3.0e38f;
#pragma unroll
        for (int j = 0; j < 8; ++j) {
            const float q = (float)((i - j) * (i - j));
            m = fminf(m, a[j] + q);
        }
        d[i] = m;
    }
}

// ---------------- fused stats + HD (+ channel EDT pass) + final ----------------
// 1024 blocks x 256 threads x 2 voxels = 524288 (b, voxel) entries
__global__ void __launch_bounds__(256) k_shd(const float* __restrict__ in, const int* __restrict__ tg,
                                             float* __restrict__ out) {
    unsigned E = (blockIdx.x * 256u + threadIdx.x) * 2u;
    unsigned v = E & (NV - 1u);
    unsigned b = E >> 18;

    float X[2][8];
#pragma unroll
    for (int c = 0; c < 8; ++c) {
        float2 t2 = *(const float2*)(in + (size_t)(b * 8 + c) * NV + v);
        X[0][c] = t2.x; X[1][c] = t2.y;
    }
    int T[2];
    { int2 tt = *(const int2*)(tg + (size_t)b * NV + v); T[0] = tt.x; T[1] = tt.y; }

    float tp[8], sP[8], cn[8];
#pragma unroll
    for (int c = 0; c < 8; ++c) { tp[c] = 0.f; sP[c] = 0.f; cn[c] = 0.f; }
    float ce = 0.0f;

#pragma unroll
    for (int k = 0; k < 2; ++k) {
        float m = X[k][0];
#pragma unroll
        for (int c = 1; c < 8; ++c) m = fmaxf(m, X[k][c]);
        float e[8]; float S = 0.f;
#pragma unroll
        for (int c = 0; c < 8; ++c) { e[c] = exp2f((X[k][c] - m) * 1.4426950408889634f); S += e[c]; }
        float r = 1.0f / S;
        int t = T[k];
        float xt = X[k][0];
#pragma unroll
        for (int c = 0; c < 8; ++c) {
            float pr = e[c] * r;
            sP[c] += pr;
            bool is = (c == t);
            tp[c] += is ? pr : 0.0f;
            cn[c] += is ? 1.0f : 0.0f;
            xt     = is ? X[k][c] : xt;
        }
        ce += (m - xt) + __log2f(S) * 0.69314718055994531f;
    }

    // HD: per field, decode combined signed field, WINDOWED channel min-plus
    // (|off|<=2, exact when result <= 9; outside pairs contribute >= 9).
    // ONE deferred fallback branch per thread; exact recompute reloads from gmem.
    float hdW = 0.0f;
    float mx = 0.0f;
#pragma unroll
    for (int field = 0; field < 2; ++field) {
        float A[2][8];
#pragma unroll
        for (int c = 0; c < 8; ++c) {
            float2 t2 = *(const float2*)(g_f + (size_t)(field * 16 + b * 8 + c) * NV + v);
            A[0][c] = t2.x; A[1][c] = t2.y;
        }
#pragma unroll
        for (int k = 0; k < 2; ++k) {
            float fgv[8], bgv[8];
#pragma unroll
            for (int c = 0; c < 8; ++c) {
                fgv[c] = fmaxf(A[k][c], 0.0f);
                bgv[c] = fmaxf(-A[k][c], 0.0f);
            }
            float dfg[8], dbg[8];
#pragma unroll
            for (int i = 0; i < 8; ++i) {
                float mf = 3.0e38f, mb = 3.0e38f;
#pragma unroll
                for (int j = 0; j < 8; ++j) {
                    const int off = i - j;
                    if (off * off <= 4) {
                        const float q = (float)(off * off);
                        mf = fminf(mf, fgv[j] + q);
                        mb = fminf(mb, bgv[j] + q);
                    }
                }
                dfg[i] = mf; dbg[i] = mb;
                mx = fmaxf(mx, fmaxf(mf, mb));
            }
            int t = T[k];
#pragma unroll
            for (int c = 0; c < 8; ++c) {
                float toh = (t == c) ? 1.0f : 0.0f;
                float pe = X[k][c] - toh;
                hdW += pe * pe * (dfg[c] + dbg[c]);
            }
        }
    }
    if (mx > 9.0f) {
        // exact cold path: recompute from gmem with full 8x8 min-plus
        hdW = 0.0f;
#pragma unroll 1
        for (int field = 0; field < 2; ++field) {
#pragma unroll 1
            for (int k = 0; k < 2; ++k) {
                float fgv[8], bgv[8];
#pragma unroll
                for (int c = 0; c < 8; ++c) {
                    float2 t2 = *(const float2*)(g_f + (size_t)(field * 16 + b * 8 + c) * NV + v);
                    float s = k ? t2.y : t2.x;
                    fgv[c] = fmaxf(s, 0.0f);
                    bgv[c] = fmaxf(-s, 0.0f);
                }
                float dfg[8], dbg[8];
                minplus8(fgv, dfg);
                minplus8(bgv, dbg);
                int t = T[k];
#pragma unroll
                for (int c = 0; c < 8; ++c) {
                    float toh = (t == c) ? 1.0f : 0.0f;
                    float pe = X[k][c] - toh;
                    hdW += pe * pe * (dfg[c] + dbg[c]);
                }
            }
        }
    }
    float hd = hdW;

    // warp reduce 26 scalars -> smem -> per-block partial stores (NO atomics)
    __shared__ float sred[26 * 8];
    int w = threadIdx.x >> 5;
#pragma unroll
    for (int c = 0; c < 8; ++c) {
        float a  = warpsum(tp[c]);
        float s2 = warpsum(sP[c]);
        float q  = warpsum(cn[c]);
        if ((threadIdx.x & 31) == 0) {
            sred[c * 8 + w]        = a;
            sred[(8 + c) * 8 + w]  = s2;
            sred[(16 + c) * 8 + w] = q;
        }
    }
    float cs = warpsum(ce);
    float hs = warpsum(hd);
    if ((threadIdx.x & 31) == 0) { sred[24 * 8 + w] = cs; sred[25 * 8 + w] = hs; }
    __syncthreads();
    if (threadIdx.x < 26) {
        int i = threadIdx.x;
        float s = 0.f;
#pragma unroll
        for (int ww = 0; ww < 8; ++ww) s += sred[i * 8 + ww];
        g_part[i][blockIdx.x] = s;
        __threadfence();             // writers only: order stores before counter
    }
    __syncthreads();

    // last block finalizes (completion counter)
    if (threadIdx.x == 0) {
        unsigned done = atomicAdd(&g_cnt, 1u);
        sred[0] = (done == gridDim.x - 1) ? 1.0f : 0.0f;
    }
    __syncthreads();
    if (sred[0] != 0.0f) {
        // reduce g_part[i][0..1023]; for i<24 split per-b: blocks [0,512) are b=0.
        __shared__ float facc[26][2];
        int lane = threadIdx.x & 31;
        int wi = threadIdx.x >> 5;       // 8 warps
#pragma unroll
        for (int iter = 0; iter < 4; ++iter) {
            int i = iter * 8 + wi;
            if (i < 26) {
                const volatile float* p = g_part[i];
                float s0 = 0.f, s1 = 0.f;
#pragma unroll
                for (int k = 0; k < 16; ++k) s0 += p[k * 32 + lane];          // blocks 0..511
#pragma unroll
                for (int k = 16; k < 32; ++k) s1 += p[k * 32 + lane];         // blocks 512..1023
                s0 = warpsum(s0); s1 = warpsum(s1);
                if (lane == 0) { facc[i][0] = s0; facc[i][1] = s1; }
            }
        }
        __syncthreads();
        if (threadIdx.x == 0) {
            float diceAcc = 0.0f;
#pragma unroll
            for (int c = 1; c < 8; ++c) {
                float sb2 = 0.0f;
#pragma unroll
                for (int bb = 0; bb < 2; ++bb) {
                    float tps = facc[c][bb];
                    float sp  = facc[8 + c][bb];
                    float cnt = facc[16 + c][bb];
                    sb2 += 2.0f * tps / (sp + cnt + 1e-5f);   // alpha=beta=1
                }
                diceAcc += 0.5f * sb2;
            }
            float dice = 1.0f - diceAcc * (1.0f / 7.0f);
            float cef = (facc[24][0] + facc[24][1]) * (1.0f / 524288.0f);
            float hdf = (facc[25][0] + facc[25][1]) * (1.0f / 4194304.0f);
            out[0] = dice + cef + hdf;
        }
    }
}

extern "C" void kernel_launch(void* const* d_in, const int* in_sizes, int n_in,
                              void* d_out, int out_size) {
    const float* in = (const float*)d_in[0];
    const int*   tg = (const int*)d_in[1];
    float* out = (float*)d_out;
    k_pass1 <<<1024, 512>>>(in, tg);
    k_pass23<<<2048, 256>>>();
    k_shd   <<<1024, 256>>>(in, tg, out);
}

// round 16
// speedup vs baseline: 1.0666x; 1.0118x over previous
#include <cuda_runtime.h>

#define NV 262144            // 64*64*64
#define BIGF 1e9f

// scratch: combined SIGNED fields, slots [field(2)][bc(16)][voxel]:
//   s = d_fg - d_bg, exactly one of (d_fg, d_bg) nonzero at every voxel.
//   Invariant holds after X pass and is preserved by Y/Z (and channel) passes.
__device__ float g_f[64ull * NV];
__device__ float g_part[26][1024];    // per-block partials, contention-free
__device__ unsigned g_cnt;

__device__ __forceinline__ float warpsum(float v) {
#pragma unroll
    for (int o = 16; o > 0; o >>= 1) v += __shfl_xor_sync(0xffffffffu, v, o);
    return v;
}

// squared dist to nearest set bit of `zeros` (BIGF if none)
__device__ __forceinline__ float dt1(unsigned long long zeros, int x) {
    unsigned long long below = zeros << (63 - x);      // bits <= x
    int dfwd = below ? __clzll((long long)below) : 1000;
    unsigned long long above = zeros >> x;             // bits >= x
    int dbwd = above ? (__ffsll((long long)above) - 1) : 1000;
    int d = min(dfwd, dbwd);
    return (d > 63) ? BIGF : (float)(d * d);
}

// quarter templated: after unroll, x is a compile-time constant -> immediate shifts
template<int Q>
__device__ __forceinline__ void p1_store(unsigned long long m, float* o) {
#pragma unroll
    for (int k = 0; k < 16; ++k) {
        const int x = Q * 16 + k;
        bool bit = ((m >> x) & 1ull) != 0ull;
        unsigned long long zz = bit ? ~m : m;        // zeros of the non-trivial side
        float dsq = dt1(zz, x);                      // always > 0
        o[(size_t)x * 4096] = bit ? dsq : -dsq;      // s = d_fg - d_bg
    }
}

// ---------------- pass 1 (axis X) ----------------
// 1024 blocks x 512 threads. Block = one (b,c,y) group of 64 z-lines.
__global__ void __launch_bounds__(512) k_pass1(const float* __restrict__ in, const int* __restrict__ tg) {
    if (blockIdx.x == 0 && threadIdx.x == 0) g_cnt = 0u;   // reset for this replay
    unsigned g = blockIdx.x;                 // (b,c,y)
    unsigned y = g & 63u, c = (g >> 6) & 7u, b = g >> 9;
    unsigned bc = b * 8u + c;
    int t = threadIdx.x;
    int z = t & 63;
    int part = t >> 6;                       // 0..7
    const float* pin = in + (size_t)bc * NV + y * 64u + z;
    const int*   ptg = tg + (size_t)b  * NV + y * 64u + z;

    unsigned m8 = 0u;                        // bits 0-7: pred, bits 8-15: tgt
#pragma unroll
    for (int k = 0; k < 8; ++k) {
        int x = part * 8 + k;
        float v = pin[(size_t)x * 4096];
        int   tt = ptg[(size_t)x * 4096];
        if (v > 0.5f)          m8 |= 1u << k;
        if ((unsigned)tt == c) m8 |= 1u << (8 + k);
    }
    __shared__ unsigned sm[512];
    sm[t] = m8;
    __syncthreads();

    int field   = part & 1;                  // 0 = pred, 1 = tgt
    int quarter = part >> 1;                 // x in [16*quarter, 16*quarter+16)
    unsigned long long m = 0ull;
#pragma unroll
    for (int p = 0; p < 8; ++p) {
        unsigned w = sm[z + p * 64];
        unsigned h8 = field ? ((w >> 8) & 0xFFu) : (w & 0xFFu);
        m |= (unsigned long long)h8 << (8 * p);
    }
    float* o = g_f + (size_t)(field * 16 + bc) * NV + y * 64u + z;
    switch (quarter) {                       // warp-uniform
        case 0: p1_store<0>(m, o); break;
        case 1: p1_store<1>(m, o); break;
        case 2: p1_store<2>(m, o); break;
        default: p1_store<3>(m, o); break;
    }
}

// ---------------- Y or Z min-plus over one line family in smem ----------------
// Exact: windowed min, pairs |i-j|<=3 (off^2<=9). If windowed min <= 16 it is
// the true min (outside pairs contribute >= 16); otherwise full-scan fallback.
// Called by ALL 512 threads (two 256-thread groups on different planes); the
// internal sync orders all reads (incl. fallback) before any writes.
template<int LSTRIDE, int LANESTRIDE>
__device__ __forceinline__ void pass_line(float* s, int t) {
    int lane = t & 63;           // orthogonal coordinate
    int h = (t >> 6) & 3;        // 0..3 -> outputs i in [16h, 16h+16)
    float* bp = s + lane * LANESTRIDE;
    int jbase = 16 * h - 3;
    float fv[22];
#pragma unroll
    for (int k = 0; k < 22; ++k) {
        int j = jbase + k;
        fv[k] = (j >= 0 && j < 64) ? bp[j * LSTRIDE] : 3.0e38f;
    }
    float d[16];
#pragma unroll
    for (int a = 0; a < 16; ++a) d[a] = 3.0e38f;
#pragma unroll
    for (int k = 0; k < 14; ++k) {
#pragma unroll
        for (int a = 0; a < 8; ++a) {
            const int off = a + 3 - k;
            if (off * off <= 9) d[a] = fminf(d[a], fv[k] + (float)(off * off));
        }
    }
#pragma unroll
    for (int k = 8; k < 22; ++k) {
#pragma unroll
        for (int a = 8; a < 16; ++a) {
            const int off = a + 3 - k;
            if (off * off <= 9) d[a] = fminf(d[a], fv[k] + (float)(off * off));
        }
    }
    float mxA = d[0], mxB = d[8];
#pragma unroll
    for (int a = 1; a < 8; ++a) { mxA = fmaxf(mxA, d[a]); mxB = fmaxf(mxB, d[a + 8]); }
    if (mxA > 16.0f) {
#pragma unroll 1
        for (int j = 0; j < 64; ++j) {
            float fj = bp[j * LSTRIDE];
#pragma unroll
            for (int a = 0; a < 8; ++a) { int dd = 16 * h + a - j; d[a] = fminf(d[a], fj + (float)(dd * dd)); }
        }
    }
    if (mxB > 16.0f) {
#pragma unroll 1
        for (int j = 0; j < 64; ++j) {
            float fj = bp[j * LSTRIDE];
#pragma unroll
            for (int a = 8; a < 16; ++a) { int dd = 16 * h + a - j; d[a] = fminf(d[a], fj + (float)(dd * dd)); }
        }
    }
    __syncthreads();   // all reads (incl. fallback) done before anyone writes
#pragma unroll
    for (int a = 0; a < 16; ++a) bp[(16 * h + a) * LSTRIDE] = d[a];
}

// 2048 blocks x 512 threads: (cvol = field*16+bc in 0..31) x (x in 0..63).
// Threads 0..255 process the fg plane, threads 256..511 the bg plane, in
// parallel. Reads ONE combined signed plane, splits, Y+Z passes, re-encodes
// s = d_fg - d_bg and writes IN PLACE.
__global__ void __launch_bounds__(512) k_pass23() {
    __shared__ float sf[64 * 65];
    __shared__ float sb[64 * 65];
    unsigned x = blockIdx.x & 63u, cvol = blockIdx.x >> 6;   // cvol < 32
    float* gio = g_f + (size_t)cvol * NV + x * 4096u;        // combined plane
    int t = threadIdx.x;
    {
        const float4* g4 = (const float4*)gio;
#pragma unroll
        for (int m = 0; m < 2; ++m) {
            int e4 = m * 512 + t;            // 1024 float4s over 512 threads
            float4 val = g4[e4];
            int e = e4 * 4;
            int y = e >> 6, z = e & 63;
            int idx = y * 65 + z;
            sf[idx + 0] = fmaxf(val.x, 0.0f); sb[idx + 0] = fmaxf(-val.x, 0.0f);
            sf[idx + 1] = fmaxf(val.y, 0.0f); sb[idx + 1] = fmaxf(-val.y, 0.0f);
            sf[idx + 2] = fmaxf(val.z, 0.0f); sb[idx + 2] = fmaxf(-val.z, 0.0f);
            sf[idx + 3] = fmaxf(val.w, 0.0f); sb[idx + 3] = fmaxf(-val.w, 0.0f);
        }
    }
    __syncthreads();
    float* s = (t < 256) ? sf : sb;          // group-uniform plane pointer
    pass_line<65, 1>(s, t);   // Y pass, both planes in parallel
    __syncthreads();          // order Y writes before Z reads
    pass_line<1, 65>(s, t);   // Z pass, both planes in parallel
    __syncthreads();          // order Z writes before the store reads
    {
        float4* g4 = (float4*)gio;
#pragma unroll
        for (int m = 0; m < 2; ++m) {
            int e4 = m * 512 + t;
            int e = e4 * 4;
            int y = e >> 6, z = e & 63;
            int idx = y * 65 + z;
            float4 val;
            val.x = sf[idx + 0] - sb[idx + 0];
            val.y = sf[idx + 1] - sb[idx + 1];
            val.z = sf[idx + 2] - sb[idx + 2];
            val.w = sf[idx + 3] - sb[idx + 3];
            g4[e4] = val;
        }
    }
}

// ---------------- full min-plus over channel axis, length 8, branchless ----------------
__device__ __forceinline__ void minplus8(const float* __restrict__ a, float* __restrict__ d) {
#pragma unroll
    for (int i = 0; i < 8; ++i) {
        float m = 3.0e38f;
#pragma unroll
        for (int j = 0; j < 8; ++j) {
            const float q = (float)((i - j) * (i - j));
            m = fminf(m, a[j] + q);
        }
        d[i] = m;
    }
}

// ---------------- fused stats + HD (+ channel EDT pass) + final ----------------
// 1024 blocks x 256 threads x 2 voxels = 524288 (b, voxel) entries
__global__ void __launch_bounds__(256) k_shd(const float* __restrict__ in, const int* __restrict__ tg,
                                             float* __restrict__ out) {
    unsigned E = (blockIdx.x * 256u + threadIdx.x) * 2u;
    unsigned v = E & (NV - 1u);
    unsigned b = E >> 18;

    float X[2][8];
#pragma unroll
    for (int c = 0; c < 8; ++c) {
        float2 t2 = *(const float2*)(in + (size_t)(b * 8 + c) * NV + v);
        X[0][c] = t2.x; X[1][c] = t2.y;
    }
    int T[2];
    { int2 tt = *(const int2*)(tg + (size_t)b * NV + v); T[0] = tt.x; T[1] = tt.y; }

    float tp[8], sP[8], cn[8];
#pragma unroll
    for (int c = 0; c < 8; ++c) { tp[c] = 0.f; sP[c] = 0.f; cn[c] = 0.f; }
    float ce = 0.0f;

#pragma unroll
    for (int k = 0; k < 2; ++k) {
        float m = X[k][0];
#pragma unroll
        for (int c = 1; c < 8; ++c) m = fmaxf(m, X[k][c]);
        float e[8]; float S = 0.f;
#pragma unroll
        for (int c = 0; c < 8; ++c) { e[c] = exp2f((X[k][c] - m) * 1.4426950408889634f); S += e[c]; }
        float r = 1.0f / S;
        int t = T[k];
        float xt = X[k][0];
#pragma unroll
        for (int c = 0; c < 8; ++c) {
            float pr = e[c] * r;
            sP[c] += pr;
            bool is = (c == t);
            tp[c] += is ? pr : 0.0f;
            cn[c] += is ? 1.0f : 0.0f;
            xt     = is ? X[k][c] : xt;
        }
        ce += (m - xt) + __log2f(S) * 0.69314718055994531f;
    }

    // HD: per field, decode combined signed field, WINDOWED channel min-plus
    // (|off|<=2, exact when result <= 9; outside pairs contribute >= 9).
    // ONE deferred fallback branch per thread; exact recompute reloads from gmem.
    float hdW = 0.0f;
    float mx = 0.0f;
#pragma unroll
    for (int field = 0; field < 2; ++field) {
        float A[2][8];
#pragma unroll
        for (int c = 0; c < 8; ++c) {
            float2 t2 = *(const float2*)(g_f + (size_t)(field * 16 + b * 8 + c) * NV + v);
            A[0][c] = t2.x; A[1][c] = t2.y;
        }
#pragma unroll
        for (int k = 0; k < 2; ++k) {
            float fgv[8], bgv[8];
#pragma unroll
            for (int c = 0; c < 8; ++c) {
                fgv[c] = fmaxf(A[k][c], 0.0f);
                bgv[c] = fmaxf(-A[k][c], 0.0f);
            }
            float dfg[8], dbg[8];
#pragma unroll
            for (int i = 0; i < 8; ++i) {
                float mf = 3.0e38f, mb = 3.0e38f;
#pragma unroll
                for (int j = 0; j < 8; ++j) {
                    const int off = i - j;
                    if (off * off <= 4) {
                        const float q = (float)(off * off);
                        mf = fminf(mf, fgv[j] + q);
                        mb = fminf(mb, bgv[j] + q);
                    }
                }
                dfg[i] = mf; dbg[i] = mb;
                mx = fmaxf(mx, fmaxf(mf, mb));
            }
            int t = T[k];
#pragma unroll
            for (int c = 0; c < 8; ++c) {
                float toh = (t == c) ? 1.0f : 0.0f;
                float pe = X[k][c] - toh;
                hdW += pe * pe * (dfg[c] + dbg[c]);
            }
        }
    }
    if (mx > 9.0f) {
        // exact cold path: recompute from gmem with full 8x8 min-plus
        hdW = 0.0f;
#pragma unroll 1
        for (int field = 0; field < 2; ++field) {
#pragma unroll 1
            for (int k = 0; k < 2; ++k) {
                float fgv[8], bgv[8];
#pragma unroll
                for (int c = 0; c < 8; ++c) {
                    float2 t2 = *(const float2*)(g_f + (size_t)(field * 16 + b * 8 + c) * NV + v);
                    float s = k ? t2.y : t2.x;
                    fgv[c] = fmaxf(s, 0.0f);
                    bgv[c] = fmaxf(-s, 0.0f);
                }
                float dfg[8], dbg[8];
                minplus8(fgv, dfg);
                minplus8(bgv, dbg);
                int t = T[k];
#pragma unroll
                for (int c = 0; c < 8; ++c) {
                    float toh = (t == c) ? 1.0f : 0.0f;
                    float pe = X[k][c] - toh;
                    hdW += pe * pe * (dfg[c] + dbg[c]);
                }
            }
        }
    }
    float hd = hdW;

    // warp reduce 26 scalars -> smem -> per-block partial stores (NO atomics)
    __shared__ float sred[26 * 8];
    int w = threadIdx.x >> 5;
#pragma unroll
    for (int c = 0; c < 8; ++c) {
        float a  = warpsum(tp[c]);
        float s2 = warpsum(sP[c]);
        float q  = warpsum(cn[c]);
        if ((threadIdx.x & 31) == 0) {
            sred[c * 8 + w]        = a;
            sred[(8 + c) * 8 + w]  = s2;
            sred[(16 + c) * 8 + w] = q;
        }
    }
    float cs = warpsum(ce);
    float hs = warpsum(hd);
    if ((threadIdx.x & 31) == 0) { sred[24 * 8 + w] = cs; sred[25 * 8 + w] = hs; }
    __syncthreads();
    if (threadIdx.x < 26) {
        int i = threadIdx.x;
        float s = 0.f;
#pragma unroll
        for (int ww = 0; ww < 8; ++ww) s += sred[i * 8 + ww];
        g_part[i][blockIdx.x] = s;
        __threadfence();             // writers only: order stores before counter
    }
    __syncthreads();

    // last block finalizes (completion counter)
    if (threadIdx.x == 0) {
        unsigned done = atomicAdd(&g_cnt, 1u);
        sred[0] = (done == gridDim.x - 1) ? 1.0f : 0.0f;
    }
    __syncthreads();
    if (sred[0] != 0.0f) {
        // reduce g_part[i][0..1023]; for i<24 split per-b: blocks [0,512) are b=0.
        __shared__ float facc[26][2];
        int lane = threadIdx.x & 31;
        int wi = threadIdx.x >> 5;       // 8 warps
#pragma unroll
        for (int iter = 0; iter < 4; ++iter) {
            int i = iter * 8 + wi;
            if (i < 26) {
                const volatile float* p = g_part[i];
                float s0 = 0.f, s1 = 0.f;
#pragma unroll
                for (int k = 0; k < 16; ++k) s0 += p[k * 32 + lane];          // blocks 0..511
#pragma unroll
                for (int k = 16; k < 32; ++k) s1 += p[k * 32 + lane];         // blocks 512..1023
                s0 = warpsum(s0); s1 = warpsum(s1);
                if (lane == 0) { facc[i][0] = s0; facc[i][1] = s1; }
            }
        }
        __syncthreads();
        if (threadIdx.x == 0) {
            float diceAcc = 0.0f;
#pragma unroll
            for (int c = 1; c < 8; ++c) {
                float sb2 = 0.0f;
#pragma unroll
                for (int bb = 0; bb < 2; ++bb) {
                    float tps = facc[c][bb];
                    float sp  = facc[8 + c][bb];
                    float cnt = facc[16 + c][bb];
                    sb2 += 2.0f * tps / (sp + cnt + 1e-5f);   // alpha=beta=1
                }
                diceAcc += 0.5f * sb2;
            }
            float dice = 1.0f - diceAcc * (1.0f / 7.0f);
            float cef = (facc[24][0] + facc[24][1]) * (1.0f / 524288.0f);
            float hdf = (facc[25][0] + facc[25][1]) * (1.0f / 4194304.0f);
            out[0] = dice + cef + hdf;
        }
    }
}

extern "C" void kernel_launch(void* const* d_in, const int* in_sizes, int n_in,
                              void* d_out, int out_size) {
    const float* in = (const float*)d_in[0];
    const int*   tg = (const int*)d_in[1];
    float* out = (float*)d_out;
    k_pass1 <<<1024, 512>>>(in, tg);
    k_pass23<<<2048, 512>>>();
    k_shd   <<<1024, 256>>>(in, tg, out);
}

// round 17
// speedup vs baseline: 1.1644x; 1.0917x over previous
#include <cuda_runtime.h>

#define NV 262144            // 64*64*64
#define BIGF 1e9f

// scratch: combined SIGNED fields, slots [field(2)][bc(16)][voxel]:
//   s = d_fg - d_bg, exactly one of (d_fg, d_bg) nonzero at every voxel.
__device__ float g_f[64ull * NV];
__device__ float g_part[26][1024];    // per-block partials, contention-free
__device__ unsigned g_cnt;

__device__ __forceinline__ float warpsum(float v) {
#pragma unroll
    for (int o = 16; o > 0; o >>= 1) v += __shfl_xor_sync(0xffffffffu, v, o);
    return v;
}

// ---------------- pass 1 chunk: 8 outputs via flip-distance recurrence ----------------
// d(x) = distance to nearest bit with opposite value (the set bits of
// zz = bit ? ~m : m). Recurrence: fwd(x) = flip(x-1,x) ? 1 : fwd(x-1)+1.
// Boundary distances come from one clz / one ffs on the full mask.
__device__ __forceinline__ void p1_chunk(unsigned long long m, int X, float* o) {
    unsigned bits = (unsigned)((m >> X) & 0xFFull);
    int fw;
    {   // fwd boundary at x = X: nearest opposite below
        unsigned long long zz = (bits & 1u) ? ~m : m;
        if (X == 0) fw = 100;                      // warp-uniform branch
        else {
            unsigned long long below = zz << (64 - X);
            fw = below ? (__clzll((long long)below) + 1) : 100;
        }
    }
    int bw[8];
    {   // bwd boundary at x = X+7: nearest opposite above
        unsigned long long zz = ((bits >> 7) & 1u) ? ~m : m;
        if (X == 56) bw[7] = 100;                  // warp-uniform branch
        else {
            unsigned long long above = zz >> (X + 8);
            bw[7] = above ? __ffsll((long long)above) : 100;
        }
    }
#pragma unroll
    for (int k = 6; k >= 0; --k) {
        bool flip = (((bits >> k) ^ (bits >> (k + 1))) & 1u) != 0u;
        bw[k] = flip ? 1 : bw[k + 1] + 1;
    }
#pragma unroll
    for (int k = 0; k < 8; ++k) {
        unsigned b = (bits >> k) & 1u;
        if (k > 0) {
            bool flip = (((bits >> k) ^ (bits >> (k - 1))) & 1u) != 0u;
            fw = flip ? 1 : fw + 1;
        }
        int d = min(fw, bw[k]);
        float dsq = (d > 63) ? BIGF : (float)(d * d);
        o[(size_t)(X + k) * 4096] = b ? dsq : -dsq; // s = d_fg - d_bg
    }
}

// ---------------- pass 1 (axis X) ----------------
// 1024 blocks x 512 threads. Block = one (b,c,y) group of 64 z-lines.
__global__ void __launch_bounds__(512) k_pass1(const float* __restrict__ in, const int* __restrict__ tg) {
    if (blockIdx.x == 0 && threadIdx.x == 0) g_cnt = 0u;   // reset for this replay
    unsigned g = blockIdx.x;                 // (b,c,y)
    unsigned y = g & 63u, c = (g >> 6) & 7u, b = g >> 9;
    unsigned bc = b * 8u + c;
    int t = threadIdx.x;
    int z = t & 63;
    int part = t >> 6;                       // 0..7
    const float* pin = in + (size_t)bc * NV + y * 64u + z;
    const int*   ptg = tg + (size_t)b  * NV + y * 64u + z;

    unsigned m8 = 0u;                        // bits 0-7: pred, bits 8-15: tgt
#pragma unroll
    for (int k = 0; k < 8; ++k) {
        int x = part * 8 + k;
        float v = pin[(size_t)x * 4096];
        int   tt = ptg[(size_t)x * 4096];
        if (v > 0.5f)          m8 |= 1u << k;
        if ((unsigned)tt == c) m8 |= 1u << (8 + k);
    }
    __shared__ unsigned sm[512];
    sm[t] = m8;
    __syncthreads();

    int field   = part & 1;                  // 0 = pred, 1 = tgt
    int quarter = part >> 1;                 // x in [16*quarter, 16*quarter+16)
    unsigned long long m = 0ull;
#pragma unroll
    for (int p = 0; p < 8; ++p) {
        unsigned w = sm[z + p * 64];
        unsigned h8 = field ? ((w >> 8) & 0xFFu) : (w & 0xFFu);
        m |= (unsigned long long)h8 << (8 * p);
    }
    float* o = g_f + (size_t)(field * 16 + bc) * NV + y * 64u + z;
    p1_chunk(m, quarter * 16,     o);
    p1_chunk(m, quarter * 16 + 8, o);
}

// ---------------- Y or Z min-plus over one line family in smem ----------------
// Exact: windowed min, pairs |i-j|<=3 (off^2<=9). If windowed min <= 16 it is
// the true min (outside pairs contribute >= 16); otherwise full-scan fallback.
template<int LSTRIDE, int LANESTRIDE>
__device__ __forceinline__ void pass_line(float* s, int t) {
    int lane = t & 63;           // orthogonal coordinate
    int h = (t >> 6) & 3;        // 0..3 -> outputs i in [16h, 16h+16)
    float* bp = s + lane * LANESTRIDE;
    int jbase = 16 * h - 3;
    float fv[22];
#pragma unroll
    for (int k = 0; k < 22; ++k) {
        int j = jbase + k;
        fv[k] = (j >= 0 && j < 64) ? bp[j * LSTRIDE] : 3.0e38f;
    }
    float d[16];
#pragma unroll
    for (int a = 0; a < 16; ++a) d[a] = 3.0e38f;
#pragma unroll
    for (int k = 0; k < 14; ++k) {
#pragma unroll
        for (int a = 0; a < 8; ++a) {
            const int off = a + 3 - k;
            if (off * off <= 9) d[a] = fminf(d[a], fv[k] + (float)(off * off));
        }
    }
#pragma unroll
    for (int k = 8; k < 22; ++k) {
#pragma unroll
        for (int a = 8; a < 16; ++a) {
            const int off = a + 3 - k;
            if (off * off <= 9) d[a] = fminf(d[a], fv[k] + (float)(off * off));
        }
    }
    float mxA = d[0], mxB = d[8];
#pragma unroll
    for (int a = 1; a < 8; ++a) { mxA = fmaxf(mxA, d[a]); mxB = fmaxf(mxB, d[a + 8]); }
    if (mxA > 16.0f) {
#pragma unroll 1
        for (int j = 0; j < 64; ++j) {
            float fj = bp[j * LSTRIDE];
#pragma unroll
            for (int a = 0; a < 8; ++a) { int dd = 16 * h + a - j; d[a] = fminf(d[a], fj + (float)(dd * dd)); }
        }
    }
    if (mxB > 16.0f) {
#pragma unroll 1
        for (int j = 0; j < 64; ++j) {
            float fj = bp[j * LSTRIDE];
#pragma unroll
            for (int a = 8; a < 16; ++a) { int dd = 16 * h + a - j; d[a] = fminf(d[a], fj + (float)(dd * dd)); }
        }
    }
    __syncthreads();   // all reads (incl. fallback) done before anyone writes
#pragma unroll
    for (int a = 0; a < 16; ++a) bp[(16 * h + a) * LSTRIDE] = d[a];
}

// 2048 blocks x 512 threads: threads 0..255 fg plane, 256..511 bg plane.
__global__ void __launch_bounds__(512) k_pass23() {
    __shared__ float sf[64 * 65];
    __shared__ float sb[64 * 65];
    unsigned x = blockIdx.x & 63u, cvol = blockIdx.x >> 6;   // cvol < 32
    float* gio = g_f + (size_t)cvol * NV + x * 4096u;        // combined plane
    int t = threadIdx.x;
    {
        const float4* g4 = (const float4*)gio;
#pragma unroll
        for (int m = 0; m < 2; ++m) {
            int e4 = m * 512 + t;            // 1024 float4s over 512 threads
            float4 val = g4[e4];
            int e = e4 * 4;
            int y = e >> 6, z = e & 63;
            int idx = y * 65 + z;
            sf[idx + 0] = fmaxf(val.x, 0.0f); sb[idx + 0] = fmaxf(-val.x, 0.0f);
            sf[idx + 1] = fmaxf(val.y, 0.0f); sb[idx + 1] = fmaxf(-val.y, 0.0f);
            sf[idx + 2] = fmaxf(val.z, 0.0f); sb[idx + 2] = fmaxf(-val.z, 0.0f);
            sf[idx + 3] = fmaxf(val.w, 0.0f); sb[idx + 3] = fmaxf(-val.w, 0.0f);
        }
    }
    __syncthreads();
    float* s = (t < 256) ? sf : sb;          // group-uniform plane pointer
    pass_line<65, 1>(s, t);   // Y pass, both planes in parallel
    __syncthreads();          // order Y writes before Z reads
    pass_line<1, 65>(s, t);   // Z pass, both planes in parallel
    __syncthreads();          // order Z writes before the store reads
    {
        float4* g4 = (float4*)gio;
#pragma unroll
        for (int m = 0; m < 2; ++m) {
            int e4 = m * 512 + t;
            int e = e4 * 4;
            int y = e >> 6, z = e & 63;
            int idx = y * 65 + z;
            float4 val;
            val.x = sf[idx + 0] - sb[idx + 0];
            val.y = sf[idx + 1] - sb[idx + 1];
            val.z = sf[idx + 2] - sb[idx + 2];
            val.w = sf[idx + 3] - sb[idx + 3];
            g4[e4] = val;
        }
    }
}

// ---------------- full min-plus over channel axis, length 8, branchless ----------------
__device__ __forceinline__ void minplus8(const float* __restrict__ a, float* __restrict__ d) {
#pragma unroll
    for (int i = 0; i < 8; ++i) {
        float m = 3.0e38f;
#pragma unroll
        for (int j = 0; j < 8; ++j) {
            const float q = (float)((i - j) * (i - j));
            m = fminf(m, a[j] + q);
        }
        d[i] = m;
    }
}

// ---------------- fused stats + HD (+ channel EDT pass) + final ----------------
// 1024 blocks x 256 threads x 2 voxels = 524288 (b, voxel) entries
__global__ void __launch_bounds__(256) k_shd(const float* __restrict__ in, const int* __restrict__ tg,
                                             float* __restrict__ out) {
    unsigned E = (blockIdx.x * 256u + threadIdx.x) * 2u;
    unsigned v = E & (NV - 1u);
    unsigned b = E >> 18;

    float X[2][8];
#pragma unroll
    for (int c = 0; c < 8; ++c) {
        float2 t2 = *(const float2*)(in + (size_t)(b * 8 + c) * NV + v);
        X[0][c] = t2.x; X[1][c] = t2.y;
    }
    int T[2];
    { int2 tt = *(const int2*)(tg + (size_t)b * NV + v); T[0] = tt.x; T[1] = tt.y; }

    float tp[8], sP[8], cn[8];
#pragma unroll
    for (int c = 0; c < 8; ++c) { tp[c] = 0.f; sP[c] = 0.f; cn[c] = 0.f; }
    float ce = 0.0f;

#pragma unroll
    for (int k = 0; k < 2; ++k) {
        float m = X[k][0];
#pragma unroll
        for (int c = 1; c < 8; ++c) m = fmaxf(m, X[k][c]);
        float e[8]; float S = 0.f;
#pragma unroll
        for (int c = 0; c < 8; ++c) { e[c] = exp2f((X[k][c] - m) * 1.4426950408889634f); S += e[c]; }
        float r = 1.0f / S;
        int t = T[k];
        float xt = X[k][0];
#pragma unroll
        for (int c = 0; c < 8; ++c) {
            float pr = e[c] * r;
            sP[c] += pr;
            bool is = (c == t);
            tp[c] += is ? pr : 0.0f;
            cn[c] += is ? 1.0f : 0.0f;
            xt     = is ? X[k][c] : xt;
        }
        ce += (m - xt) + __log2f(S) * 0.69314718055994531f;
    }

    // HD: per field, decode combined signed field, WINDOWED channel min-plus
    // (|off|<=2, exact when result <= 9; outside pairs contribute >= 9).
    // ONE deferred fallback branch per thread; exact recompute reloads from gmem.
    float hdW = 0.0f;
    float mx = 0.0f;
#pragma unroll
    for (int field = 0; field < 2; ++field) {
        float A[2][8];
#pragma unroll
        for (int c = 0; c < 8; ++c) {
            float2 t2 = *(const float2*)(g_f + (size_t)(field * 16 + b * 8 + c) * NV + v);
            A[0][c] = t2.x; A[1][c] = t2.y;
        }
#pragma unroll
        for (int k = 0; k < 2; ++k) {
            float fgv[8], bgv[8];
#pragma unroll
            for (int c = 0; c < 8; ++c) {
                fgv[c] = fmaxf(A[k][c], 0.0f);
                bgv[c] = fmaxf(-A[k][c], 0.0f);
            }
            float dfg[8], dbg[8];
#pragma unroll
            for (int i = 0; i < 8; ++i) {
                float mf = 3.0e38f, mb = 3.0e38f;
#pragma unroll
                for (int j = 0; j < 8; ++j) {
                    const int off = i - j;
                    if (off * off <= 4) {
                        const float q = (float)(off * off);
                        mf = fminf(mf, fgv[j] + q);
                        mb = fminf(mb, bgv[j] + q);
                    }
                }
                dfg[i] = mf; dbg[i] = mb;
                mx = fmaxf(mx, fmaxf(mf, mb));
            }
            int t = T[k];
#pragma unroll
            for (int c = 0; c < 8; ++c) {
                float toh = (t == c) ? 1.0f : 0.0f;
                float pe = X[k][c] - toh;
                hdW += pe * pe * (dfg[c] + dbg[c]);
            }
        }
    }
    if (mx > 9.0f) {
        // exact cold path: recompute from gmem with full 8x8 min-plus
        hdW = 0.0f;
#pragma unroll 1
        for (int field = 0; field < 2; ++field) {
#pragma unroll 1
            for (int k = 0; k < 2; ++k) {
                float fgv[8], bgv[8];
#pragma unroll
                for (int c = 0; c < 8; ++c) {
                    float2 t2 = *(const float2*)(g_f + (size_t)(field * 16 + b * 8 + c) * NV + v);
                    float s = k ? t2.y : t2.x;
                    fgv[c] = fmaxf(s, 0.0f);
                    bgv[c] = fmaxf(-s, 0.0f);
                }
                float dfg[8], dbg[8];
                minplus8(fgv, dfg);
                minplus8(bgv, dbg);
                int t = T[k];
#pragma unroll
                for (int c = 0; c < 8; ++c) {
                    float toh = (t == c) ? 1.0f : 0.0f;
                    float pe = X[k][c] - toh;
                    hdW += pe * pe * (dfg[c] + dbg[c]);
                }
            }
        }
    }
    float hd = hdW;

    // warp reduce 26 scalars -> smem -> per-block partial stores (NO atomics)
    __shared__ float sred[26 * 8];
    int w = threadIdx.x >> 5;
#pragma unroll
    for (int c = 0; c < 8; ++c) {
        float a  = warpsum(tp[c]);
        float s2 = warpsum(sP[c]);
        float q  = warpsum(cn[c]);
        if ((threadIdx.x & 31) == 0) {
            sred[c * 8 + w]        = a;
            sred[(8 + c) * 8 + w]  = s2;
            sred[(16 + c) * 8 + w] = q;
        }
    }
    float cs = warpsum(ce);
    float hs = warpsum(hd);
    if ((threadIdx.x & 31) == 0) { sred[24 * 8 + w] = cs; sred[25 * 8 + w] = hs; }
    __syncthreads();
    if (threadIdx.x < 26) {
        int i = threadIdx.x;
        float s = 0.f;
#pragma unroll
        for (int ww = 0; ww < 8; ++ww) s += sred[i * 8 + ww];
        g_part[i][blockIdx.x] = s;
        __threadfence();             // writers only: order stores before counter
    }
    __syncthreads();

    // last block finalizes (completion counter)
    if (threadIdx.x == 0) {
        unsigned done = atomicAdd(&g_cnt, 1u);
        sred[0] = (done == gridDim.x - 1) ? 1.0f : 0.0f;
    }
    __syncthreads();
    if (sred[0] != 0.0f) {
        // reduce g_part[i][0..1023]; for i<24 split per-b: blocks [0,512) are b=0.
        __shared__ float facc[26][2];
        int lane = threadIdx.x & 31;
        int wi = threadIdx.x >> 5;       // 8 warps
#pragma unroll
        for (int iter = 0; iter < 4; ++iter) {
            int i = iter * 8 + wi;
            if (i < 26) {
                const volatile float* p = g_part[i];
                float s0 = 0.f, s1 = 0.f;
#pragma unroll
                for (int k = 0; k < 16; ++k) s0 += p[k * 32 + lane];          // blocks 0..511
#pragma unroll
                for (int k = 16; k < 32; ++k) s1 += p[k * 32 + lane];         // blocks 512..1023
                s0 = warpsum(s0); s1 = warpsum(s1);
                if (lane == 0) { facc[i][0] = s0; facc[i][1] = s1; }
            }
        }
        __syncthreads();
        if (threadIdx.x == 0) {
            float diceAcc = 0.0f;
#pragma unroll
            for (int c = 1; c < 8; ++c) {
                float sb2 = 0.0f;
#pragma unroll
                for (int bb = 0; bb < 2; ++bb) {
                    float tps = facc[c][bb];
                    float sp  = facc[8 + c][bb];
                    float cnt = facc[16 + c][bb];
                    sb2 += 2.0f * tps / (sp + cnt + 1e-5f);   // alpha=beta=1
                }
                diceAcc += 0.5f * sb2;
            }
            float dice = 1.0f - diceAcc * (1.0f / 7.0f);
            float cef = (facc[24][0] + facc[24][1]) * (1.0f / 524288.0f);
            float hdf = (facc[25][0] + facc[25][1]) * (1.0f / 4194304.0f);
            out[0] = dice + cef + hdf;
        }
    }
}

extern "C" void kernel_launch(void* const* d_in, const int* in_sizes, int n_in,
                              void* d_out, int out_size) {
    const float* in = (const float*)d_in[0];
    const int*   tg = (const int*)d_in[1];
    float* out = (float*)d_out;
    k_pass1 <<<1024, 512>>>(in, tg);
    k_pass23<<<2048, 512>>>();
    k_shd   <<<1024, 256>>>(in, tg, out);
}